// round 1
// baseline (speedup 1.0000x reference)
#include <cuda_runtime.h>

#define BB 32
#define TT 1024
#define RR 8
#define CC 32
#define NPRD 128
#define RCDIM 256
#define HIDD 1024
#define NLAT 160
#define RKEEP 6

// scratch (no allocations allowed)
__device__ float g_M[NLAT * RCDIM];      // M = V_W @ U_W  (160 x 256)
__device__ float g_biasb[BB * NLAT];     // per-batch fused bias (32 x 160)

__device__ __forceinline__ unsigned f2tf(float x) {
    unsigned r;
    asm("cvt.rna.tf32.f32 %0, %1;" : "=r"(r) : "f"(x));
    return r;
}

__device__ __forceinline__ void mma8(float* c,
                                     unsigned a0, unsigned a1, unsigned a2, unsigned a3,
                                     unsigned b0, unsigned b1) {
    asm volatile(
        "mma.sync.aligned.m16n8k8.row.col.f32.tf32.tf32.f32 "
        "{%0,%1,%2,%3}, {%4,%5,%6,%7}, {%8,%9}, {%0,%1,%2,%3};"
        : "+f"(c[0]), "+f"(c[1]), "+f"(c[2]), "+f"(c[3])
        : "r"(a0), "r"(a1), "r"(a2), "r"(a3), "r"(b0), "r"(b1));
}

// ---------------------------------------------------------------------------
// P1: M[l][rc] = sum_i V_W[l][i] * U_W[i][rc]
// grid 160 blocks: 10 (l-tiles of 16) x 16 (rc-tiles of 16), 256 threads
// ---------------------------------------------------------------------------
__global__ void __launch_bounds__(256) p1_kernel(const float* __restrict__ V_W,
                                                 const float* __restrict__ U_W) {
    __shared__ float Vs[16 * 68];
    __shared__ float Us[64 * 20];
    const int tid = threadIdx.x;
    const int lt = (blockIdx.x >> 4) * 16;
    const int ct = (blockIdx.x & 15) * 16;
    const int i = tid >> 4, jj = tid & 15;
    float acc = 0.f;
    for (int k0 = 0; k0 < HIDD; k0 += 64) {
        float4 v = *(const float4*)(V_W + (size_t)(lt + (tid >> 4)) * HIDD + k0 + (tid & 15) * 4);
        *(float4*)(Vs + (tid >> 4) * 68 + (tid & 15) * 4) = v;
        float4 u = *(const float4*)(U_W + (size_t)(k0 + (tid >> 2)) * RCDIM + ct + (tid & 3) * 4);
        *(float4*)(Us + (tid >> 2) * 20 + (tid & 3) * 4) = u;
        __syncthreads();
#pragma unroll
        for (int kk = 0; kk < 64; kk++)
            acc += Vs[i * 68 + kk] * Us[kk * 20 + jj];
        __syncthreads();
    }
    g_M[(lt + i) * RCDIM + ct + jj] = acc;
}

// ---------------------------------------------------------------------------
// P2: bias2[l] = V_W[l]·U_b + V_b[l];
//     biasb[b][l] = bias2[l] + sum_{kept r, c} M[l][32r+c] * b_area[r][c]
// grid 160 blocks (one per l), 128 threads
// ---------------------------------------------------------------------------
__global__ void __launch_bounds__(128) p2_kernel(const float* __restrict__ V_W,
                                                 const float* __restrict__ U_b,
                                                 const float* __restrict__ V_b,
                                                 const float* __restrict__ b_area,
                                                 const int* __restrict__ ids) {
    __shared__ float red[128];
    const int l = blockIdx.x, tid = threadIdx.x;
    float s = 0.f;
    for (int i = tid; i < HIDD; i += 128) s += V_W[(size_t)l * HIDD + i] * U_b[i];
    red[tid] = s;
    __syncthreads();
    for (int st = 64; st > 0; st >>= 1) {
        if (tid < st) red[tid] += red[tid + st];
        __syncthreads();
    }
    const float bias2 = red[0] + V_b[l];
    if (tid < BB) {
        const int b = tid;
        float s2 = bias2;
#pragma unroll
        for (int j = 0; j < RKEEP; j++) {
            const int r = ids[b * RR + j];
            const float* Mrow = g_M + l * RCDIM + r * CC;
            const float* ba = b_area + r * CC;
#pragma unroll
            for (int c = 0; c < CC; c++) s2 += Mrow[c] * ba[c];
        }
        g_biasb[b * NLAT + l] = s2;
    }
}

// ---------------------------------------------------------------------------
// Main fused kernel. grid = (8 t-tiles, 32 batches), 512 threads.
// Per kept region r:
//   stage1:  h(128x32) = x_tile(128x128) @ W_area[r](32x128)^T   (tf32 MMA)
//   stage2:  out(128x160) += h(128x32) @ M[:,32r:32r+32]^T        (tf32 MMA)
// Epilogue: out += biasb[b]
// ---------------------------------------------------------------------------
constexpr int XS = 132;   // x_s / w_s row stride (floats): 132 % 32 == 4 -> conflict-free frag LDS
constexpr int HS = 36;    // h_s / m_s row stride
constexpr int X_OFF = 0;
constexpr int W_OFF = X_OFF + 128 * XS;
constexpr int H_OFF = W_OFF + 32 * XS;
constexpr int M_OFF = H_OFF + 128 * HS;
constexpr int B_OFF = M_OFF + 160 * HS;
constexpr int K_OFF = B_OFF + 160;
constexpr int SMEM_BYTES = (K_OFF + 8) * 4;   // 126,624 B

__global__ void __launch_bounds__(512, 1) main_kernel(const float* __restrict__ spikes,
                                                      const float* __restrict__ W_area,
                                                      const int* __restrict__ ids,
                                                      float* __restrict__ out) {
    extern __shared__ float sm[];
    float* x_s = sm + X_OFF;
    float* w_s = sm + W_OFF;
    float* h_s = sm + H_OFF;
    float* m_s = sm + M_OFF;
    float* bias_s = sm + B_OFF;
    int* kept_s = (int*)(sm + K_OFF);

    const int tid = threadIdx.x;
    const int wid = tid >> 5, lane = tid & 31;
    const int g = lane >> 2, tig = lane & 3;
    const int b = blockIdx.y, t0 = blockIdx.x * 128;

    if (tid < NLAT) bias_s[tid] = g_biasb[b * NLAT + tid];
    if (tid < RKEEP) kept_s[tid] = ids[b * RR + tid];

    // stage1 warp mapping: 8 m-tiles (16 rows) x 2 n-halves (16 cols)
    const int mt = wid >> 1, nh = wid & 1;
    // stage2 warp mapping: 4 m-groups (32 rows) x 4 n-groups (40 cols)
    const int mg = wid >> 2, ng = wid & 3;

    float acc[2][5][4];
#pragma unroll
    for (int a = 0; a < 2; a++)
#pragma unroll
        for (int n = 0; n < 5; n++)
#pragma unroll
            for (int q = 0; q < 4; q++) acc[a][n][q] = 0.f;

    const size_t xbase = ((size_t)b * TT + t0) * (size_t)(RR * NPRD);

    for (int j = 0; j < RKEEP; j++) {
        __syncthreads();  // kept_s ready / previous stage2 done with smem
        const int r = kept_s[j];

        // ---- load x tile: 128 rows x 128 floats ----
        const float4* xg = (const float4*)(spikes + xbase + (size_t)r * NPRD);
#pragma unroll
        for (int k = 0; k < 8; k++) {
            const int idx = tid + k * 512;
            const int row = idx >> 5, c4 = idx & 31;
            *(float4*)(x_s + row * XS + c4 * 4) = xg[(size_t)row * 256 + c4];
        }
        // ---- load W_area[r]: 32 rows x 128 floats ----
        const float4* wg = (const float4*)(W_area + (size_t)r * CC * NPRD);
#pragma unroll
        for (int k = 0; k < 2; k++) {
            const int idx = tid + k * 512;
            const int row = idx >> 5, c4 = idx & 31;
            *(float4*)(w_s + row * XS + c4 * 4) = wg[row * 32 + c4];
        }
        // ---- load M slice: 160 rows x 32 floats ----
#pragma unroll
        for (int k = 0; k < 3; k++) {
            const int idx = tid + k * 512;
            if (idx < 1280) {
                const int row = idx >> 3, c4 = idx & 7;
                *(float4*)(m_s + row * HS + c4 * 4) =
                    *(const float4*)(g_M + row * RCDIM + r * CC + c4 * 4);
            }
        }
        __syncthreads();

        // ---- stage 1: h = x @ W^T, K = 128 (16 k-steps) ----
        float hacc[2][4];
#pragma unroll
        for (int n = 0; n < 2; n++)
#pragma unroll
            for (int q = 0; q < 4; q++) hacc[n][q] = 0.f;
        {
            const float* xa = x_s + mt * 16 * XS;
#pragma unroll
            for (int ks = 0; ks < 16; ks++) {
                const float* xp = xa + ks * 8;
                const unsigned a0 = f2tf(xp[g * XS + tig]);
                const unsigned a1 = f2tf(xp[(g + 8) * XS + tig]);
                const unsigned a2 = f2tf(xp[g * XS + tig + 4]);
                const unsigned a3 = f2tf(xp[(g + 8) * XS + tig + 4]);
#pragma unroll
                for (int nt = 0; nt < 2; nt++) {
                    const float* wp = w_s + (nh * 16 + nt * 8 + g) * XS + ks * 8;
                    const unsigned b0 = f2tf(wp[tig]);
                    const unsigned b1 = f2tf(wp[tig + 4]);
                    mma8(hacc[nt], a0, a1, a2, a3, b0, b1);
                }
            }
        }
        // store h to smem, pre-rounded to tf32 for stage2 A-operand
#pragma unroll
        for (int nt = 0; nt < 2; nt++) {
            const int col = nh * 16 + nt * 8 + 2 * tig;
            float* hp0 = h_s + (mt * 16 + g) * HS + col;
            hp0[0] = __uint_as_float(f2tf(hacc[nt][0]));
            hp0[1] = __uint_as_float(f2tf(hacc[nt][1]));
            float* hp1 = h_s + (mt * 16 + g + 8) * HS + col;
            hp1[0] = __uint_as_float(f2tf(hacc[nt][2]));
            hp1[1] = __uint_as_float(f2tf(hacc[nt][3]));
        }
        __syncthreads();

        // ---- stage 2: out += h @ M_r^T, K = 32 (4 k-steps) ----
#pragma unroll
        for (int ks = 0; ks < 4; ks++) {
            unsigned A[2][4];
#pragma unroll
            for (int m2 = 0; m2 < 2; m2++) {
                const float* hp = h_s + (mg * 32 + m2 * 16) * HS + ks * 8;
                A[m2][0] = __float_as_uint(hp[g * HS + tig]);
                A[m2][1] = __float_as_uint(hp[(g + 8) * HS + tig]);
                A[m2][2] = __float_as_uint(hp[g * HS + tig + 4]);
                A[m2][3] = __float_as_uint(hp[(g + 8) * HS + tig + 4]);
            }
#pragma unroll
            for (int nt = 0; nt < 5; nt++) {
                const float* mp = m_s + (ng * 40 + nt * 8 + g) * HS + ks * 8;
                const unsigned b0 = f2tf(mp[tig]);
                const unsigned b1 = f2tf(mp[tig + 4]);
                mma8(acc[0][nt], A[0][0], A[0][1], A[0][2], A[0][3], b0, b1);
                mma8(acc[1][nt], A[1][0], A[1][1], A[1][2], A[1][3], b0, b1);
            }
        }
    }

    // ---- epilogue: add per-batch bias, store ----
    float* og = out + ((size_t)b * TT + t0) * NLAT;
#pragma unroll
    for (int m2 = 0; m2 < 2; m2++) {
        const int row0 = mg * 32 + m2 * 16 + g;
#pragma unroll
        for (int nt = 0; nt < 5; nt++) {
            const int col = ng * 40 + nt * 8 + 2 * tig;
            const float blo = bias_s[col], bhi = bias_s[col + 1];
            float2 v0 = make_float2(acc[m2][nt][0] + blo, acc[m2][nt][1] + bhi);
            *(float2*)(og + (size_t)row0 * NLAT + col) = v0;
            float2 v1 = make_float2(acc[m2][nt][2] + blo, acc[m2][nt][3] + bhi);
            *(float2*)(og + (size_t)(row0 + 8) * NLAT + col) = v1;
        }
    }
}

extern "C" void kernel_launch(void* const* d_in, const int* in_sizes, int n_in,
                              void* d_out, int out_size) {
    const float* spikes = (const float*)d_in[0];
    const float* W_area = (const float*)d_in[1];
    const float* b_area = (const float*)d_in[2];
    const float* U_W    = (const float*)d_in[3];
    const float* U_b    = (const float*)d_in[4];
    const float* V_W    = (const float*)d_in[5];
    const float* V_b    = (const float*)d_in[6];
    const int*   ids    = (const int*)d_in[7];
    float* out = (float*)d_out;

    cudaFuncSetAttribute(main_kernel, cudaFuncAttributeMaxDynamicSharedMemorySize, SMEM_BYTES);

    p1_kernel<<<160, 256>>>(V_W, U_W);
    p2_kernel<<<160, 128>>>(V_W, U_b, V_b, b_area, ids);
    main_kernel<<<dim3(8, 32), 512, SMEM_BYTES>>>(spikes, W_area, ids, out);
}